// round 1
// baseline (speedup 1.0000x reference)
#include <cuda_runtime.h>
#include <math.h>

#define BB 4
#define NN 1024
#define DD 768
#define HH 12
#define HD 64
#define MROWS (BB*NN)          // 4096

// ---------------- scratch (no allocations allowed) ----------------
__device__ float g_q[BB*HH*NN*HD];
__device__ float g_k[BB*HH*NN*HD];
__device__ float g_v[BB*HH*NN*HD];
__device__ float g_att[BB*NN*DD];
__device__ int   g_cx[BB*NN];
__device__ int   g_cy[BB*NN];

// ---------------- prep: integer grid coords ----------------
__global__ void prep_kernel(const float* __restrict__ coords) {
    int i = blockIdx.x * blockDim.x + threadIdx.x;
    if (i < BB*NN) {
        g_cx[i] = (int)(coords[2*i + 0] * 128.0f);
        g_cy[i] = (int)(coords[2*i + 1] * 128.0f);
    }
}

// ---------------- QKV GEMM: [4096,768] x [2304,768]^T ----------------
// BM=BN=128, BK=8, 256 threads, 8x8 per thread. Epilogue scatters to q/k/v
// in [B,H,N,hd] layout, q pre-scaled by hd^-0.5 = 0.125.
__global__ __launch_bounds__(256) void qkv_gemm(const float* __restrict__ X,
                                                const float* __restrict__ W,
                                                const float* __restrict__ bias) {
    __shared__ float As[8][128];
    __shared__ float Bs[8][128];
    int tid = threadIdx.x;
    int tx = tid & 15, ty = tid >> 4;
    int row0 = blockIdx.y * 128;
    int col0 = blockIdx.x * 128;

    float acc[8][8];
#pragma unroll
    for (int i = 0; i < 8; i++)
#pragma unroll
        for (int j = 0; j < 8; j++) acc[i][j] = 0.0f;

    int lr = tid >> 1;           // 0..127
    int lk = (tid & 1) * 4;      // 0 or 4
    const float* Aptr = X + (size_t)(row0 + lr) * DD + lk;
    const float* Bptr = W + (size_t)(col0 + lr) * DD + lk;

    for (int kt = 0; kt < DD; kt += 8) {
        float4 a4 = *(const float4*)(Aptr + kt);
        float4 b4 = *(const float4*)(Bptr + kt);
        As[lk+0][lr] = a4.x; As[lk+1][lr] = a4.y; As[lk+2][lr] = a4.z; As[lk+3][lr] = a4.w;
        Bs[lk+0][lr] = b4.x; Bs[lk+1][lr] = b4.y; Bs[lk+2][lr] = b4.z; Bs[lk+3][lr] = b4.w;
        __syncthreads();
#pragma unroll
        for (int kk = 0; kk < 8; kk++) {
            float a[8], b[8];
            *(float4*)(a)     = *(const float4*)&As[kk][ty*8];
            *(float4*)(a + 4) = *(const float4*)&As[kk][ty*8 + 4];
            *(float4*)(b)     = *(const float4*)&Bs[kk][tx*8];
            *(float4*)(b + 4) = *(const float4*)&Bs[kk][tx*8 + 4];
#pragma unroll
            for (int i = 0; i < 8; i++)
#pragma unroll
                for (int j = 0; j < 8; j++) acc[i][j] = fmaf(a[i], b[j], acc[i][j]);
        }
        __syncthreads();
    }

#pragma unroll
    for (int i = 0; i < 8; i++) {
        int m = row0 + ty*8 + i;
        int bidx = m >> 10;          // /1024
        int n    = m & 1023;
#pragma unroll
        for (int j = 0; j < 8; j++) {
            int jg = col0 + tx*8 + j;
            int which = jg / DD;
            int rem   = jg - which * DD;
            int h     = rem >> 6;
            int dd    = rem & 63;
            float v = acc[i][j] + bias[jg];
            size_t off = (((size_t)(bidx*HH + h))*NN + n)*HD + dd;
            if (which == 0)      g_q[off] = v * 0.125f;
            else if (which == 1) g_k[off] = v;
            else                 g_v[off] = v;
        }
    }
}

// ---------------- output projection: [4096,768] x [768,768]^T ----------------
__global__ __launch_bounds__(256) void proj_gemm(const float* __restrict__ W,
                                                 const float* __restrict__ bias,
                                                 float* __restrict__ out) {
    __shared__ float As[8][128];
    __shared__ float Bs[8][128];
    int tid = threadIdx.x;
    int tx = tid & 15, ty = tid >> 4;
    int row0 = blockIdx.y * 128;
    int col0 = blockIdx.x * 128;

    float acc[8][8];
#pragma unroll
    for (int i = 0; i < 8; i++)
#pragma unroll
        for (int j = 0; j < 8; j++) acc[i][j] = 0.0f;

    int lr = tid >> 1;
    int lk = (tid & 1) * 4;
    const float* Aptr = g_att + (size_t)(row0 + lr) * DD + lk;
    const float* Bptr = W + (size_t)(col0 + lr) * DD + lk;

    for (int kt = 0; kt < DD; kt += 8) {
        float4 a4 = *(const float4*)(Aptr + kt);
        float4 b4 = *(const float4*)(Bptr + kt);
        As[lk+0][lr] = a4.x; As[lk+1][lr] = a4.y; As[lk+2][lr] = a4.z; As[lk+3][lr] = a4.w;
        Bs[lk+0][lr] = b4.x; Bs[lk+1][lr] = b4.y; Bs[lk+2][lr] = b4.z; Bs[lk+3][lr] = b4.w;
        __syncthreads();
#pragma unroll
        for (int kk = 0; kk < 8; kk++) {
            float a[8], b[8];
            *(float4*)(a)     = *(const float4*)&As[kk][ty*8];
            *(float4*)(a + 4) = *(const float4*)&As[kk][ty*8 + 4];
            *(float4*)(b)     = *(const float4*)&Bs[kk][tx*8];
            *(float4*)(b + 4) = *(const float4*)&Bs[kk][tx*8 + 4];
#pragma unroll
            for (int i = 0; i < 8; i++)
#pragma unroll
                for (int j = 0; j < 8; j++) acc[i][j] = fmaf(a[i], b[j], acc[i][j]);
        }
        __syncthreads();
    }

#pragma unroll
    for (int i = 0; i < 8; i++) {
        int m = row0 + ty*8 + i;
#pragma unroll
        for (int j = 0; j < 8; j++) {
            int jg = col0 + tx*8 + j;
            out[(size_t)m * DD + jg] = acc[i][j] + bias[jg];
        }
    }
}

// ---------------- fused attention (flash-style) ----------------
#define BR 64
#define BC 64
#define SP 65
// smem: qs + ks + vs (64*65 floats each) + er/ec (64 each) + lut(260) + 4*64 ints
#define ATTN_SMEM_BYTES ((3*64*SP + 2*64) * 4 + (260 + 4*64) * 4)

__global__ __launch_bounds__(256) void attn_kernel(const float* __restrict__ elev,
                                                   const float* __restrict__ btab,
                                                   const float* __restrict__ alpha_p) {
    extern __shared__ float smf[];
    float* qs = smf;                    // [64][65]
    float* ks = qs + 64*SP;             // [64][65], reused for P
    float* vs = ks + 64*SP;             // [64][65]
    float* er = vs + 64*SP;             // [64]
    float* ec = er + 64;                // [64]
    int*   lut = (int*)(ec + 64);       // [260]
    int*   cxr = lut + 260;
    int*   cyr = cxr + 64;
    int*   cxc = cyr + 64;
    int*   cyc = cxc + 64;

    int tid = threadIdx.x;
    int tx = tid & 15, ty = tid >> 4;
    int ty4 = ty * 4, tx4 = tx * 4;
    int r0 = blockIdx.x * BR;
    int h  = blockIdx.y;
    int b  = blockIdx.z;
    float alpha = alpha_p[0];

    // bucket LUT: bucket of rel in [-128,128] at lut[rel+128]
    for (int i = tid; i < 257; i += 256) {
        int rel = i - 128;
        int neg = -rel;
        int ret = (neg < 0) ? 16 : 0;
        int a = (neg < 0) ? -neg : neg;
        int bv;
        if (a < 8) bv = a;
        else {
            float t = logf((float)a * 0.125f) / 2.7725887222397811f * 8.0f;
            bv = 8 + (int)t;
            if (bv > 15) bv = 15;
        }
        lut[i] = ret + bv;
    }

    // load Q rows + row metadata
    const float* qptr = g_q + (((size_t)(b*HH + h))*NN + r0)*HD;
    for (int e = tid; e < BR*HD/4; e += 256) {
        int lr = e >> 4;
        int d4 = (e & 15) << 2;
        float4 q4 = *(const float4*)(qptr + lr*HD + d4);
        qs[lr*SP + d4 + 0] = q4.x; qs[lr*SP + d4 + 1] = q4.y;
        qs[lr*SP + d4 + 2] = q4.z; qs[lr*SP + d4 + 3] = q4.w;
    }
    if (tid < 64) {
        int gr = b*NN + r0 + tid;
        cxr[tid] = g_cx[gr]; cyr[tid] = g_cy[gr]; er[tid] = elev[gr];
    }

    float m_i[4], l_i[4], O[4][4];
#pragma unroll
    for (int i = 0; i < 4; i++) {
        m_i[i] = -INFINITY; l_i[i] = 0.0f;
#pragma unroll
        for (int j = 0; j < 4; j++) O[i][j] = 0.0f;
    }

    const float* kbase = g_k + ((size_t)(b*HH + h))*NN*HD;
    const float* vbase = g_v + ((size_t)(b*HH + h))*NN*HD;

    for (int t = 0; t < NN/BC; t++) {
        int c0 = t * BC;
        __syncthreads();   // previous PV done with ks/vs
        for (int e = tid; e < BC*HD/4; e += 256) {
            int lc = e >> 4;
            int d4 = (e & 15) << 2;
            float4 k4 = *(const float4*)(kbase + (size_t)(c0+lc)*HD + d4);
            ks[lc*SP + d4 + 0] = k4.x; ks[lc*SP + d4 + 1] = k4.y;
            ks[lc*SP + d4 + 2] = k4.z; ks[lc*SP + d4 + 3] = k4.w;
            float4 v4 = *(const float4*)(vbase + (size_t)(c0+lc)*HD + d4);
            vs[lc*SP + d4 + 0] = v4.x; vs[lc*SP + d4 + 1] = v4.y;
            vs[lc*SP + d4 + 2] = v4.z; vs[lc*SP + d4 + 3] = v4.w;
        }
        if (tid < 64) {
            int gc = b*NN + c0 + tid;
            cxc[tid] = g_cx[gc]; cyc[tid] = g_cy[gc]; ec[tid] = elev[gc];
        }
        __syncthreads();

        // S = q . k^T  (q already scaled)
        float s[4][4];
#pragma unroll
        for (int i = 0; i < 4; i++)
#pragma unroll
            for (int j = 0; j < 4; j++) s[i][j] = 0.0f;
#pragma unroll 8
        for (int d = 0; d < HD; d++) {
            float a0 = qs[(ty4+0)*SP + d];
            float a1 = qs[(ty4+1)*SP + d];
            float a2 = qs[(ty4+2)*SP + d];
            float a3 = qs[(ty4+3)*SP + d];
            float b0 = ks[(tx4+0)*SP + d];
            float b1 = ks[(tx4+1)*SP + d];
            float b2 = ks[(tx4+2)*SP + d];
            float b3 = ks[(tx4+3)*SP + d];
            s[0][0] = fmaf(a0,b0,s[0][0]); s[0][1] = fmaf(a0,b1,s[0][1]);
            s[0][2] = fmaf(a0,b2,s[0][2]); s[0][3] = fmaf(a0,b3,s[0][3]);
            s[1][0] = fmaf(a1,b0,s[1][0]); s[1][1] = fmaf(a1,b1,s[1][1]);
            s[1][2] = fmaf(a1,b2,s[1][2]); s[1][3] = fmaf(a1,b3,s[1][3]);
            s[2][0] = fmaf(a2,b0,s[2][0]); s[2][1] = fmaf(a2,b1,s[2][1]);
            s[2][2] = fmaf(a2,b2,s[2][2]); s[2][3] = fmaf(a2,b3,s[2][3]);
            s[3][0] = fmaf(a3,b0,s[3][0]); s[3][1] = fmaf(a3,b1,s[3][1]);
            s[3][2] = fmaf(a3,b2,s[3][2]); s[3][3] = fmaf(a3,b3,s[3][3]);
        }
        __syncthreads();   // all S reads of ks done; safe to overwrite with P

        // biases + online softmax
#pragma unroll
        for (int i = 0; i < 4; i++) {
            int lr = ty4 + i;
            int cxi = cxr[lr], cyi = cyr[lr];
            float ei = er[lr];
#pragma unroll
            for (int j = 0; j < 4; j++) {
                int lc = tx4 + j;
                int bx = lut[cxi - cxc[lc] + 128];
                int by = lut[cyi - cyc[lc] + 128];
                float rb = __ldg(btab + (bx*32 + by)*HH + h);
                float diff = (ec[lc] - ei) / 1000.0f;
                float eb = fminf(fmaxf(-alpha * fmaxf(diff, 0.0f), -10.0f), 0.0f);
                s[i][j] += rb + eb;
            }
            float rm = fmaxf(fmaxf(s[i][0], s[i][1]), fmaxf(s[i][2], s[i][3]));
#pragma unroll
            for (int off = 1; off < 16; off <<= 1)
                rm = fmaxf(rm, __shfl_xor_sync(0xffffffffu, rm, off));
            float mn = fmaxf(m_i[i], rm);
            float corr = __expf(m_i[i] - mn);
            m_i[i] = mn;
            float rs = 0.0f;
#pragma unroll
            for (int j = 0; j < 4; j++) {
                float p = __expf(s[i][j] - mn);
                s[i][j] = p;
                rs += p;
            }
#pragma unroll
            for (int off = 1; off < 16; off <<= 1)
                rs += __shfl_xor_sync(0xffffffffu, rs, off);
            l_i[i] = l_i[i] * corr + rs;
#pragma unroll
            for (int j = 0; j < 4; j++) {
                O[i][j] *= corr;
                ks[lr*SP + tx4 + j] = s[i][j];   // P tile over K
            }
        }
        __syncthreads();

        // O += P . V
#pragma unroll 8
        for (int c = 0; c < BC; c++) {
            float p0 = ks[(ty4+0)*SP + c];
            float p1 = ks[(ty4+1)*SP + c];
            float p2 = ks[(ty4+2)*SP + c];
            float p3 = ks[(ty4+3)*SP + c];
            float v0 = vs[c*SP + tx4 + 0];
            float v1 = vs[c*SP + tx4 + 1];
            float v2 = vs[c*SP + tx4 + 2];
            float v3 = vs[c*SP + tx4 + 3];
            O[0][0] = fmaf(p0,v0,O[0][0]); O[0][1] = fmaf(p0,v1,O[0][1]);
            O[0][2] = fmaf(p0,v2,O[0][2]); O[0][3] = fmaf(p0,v3,O[0][3]);
            O[1][0] = fmaf(p1,v0,O[1][0]); O[1][1] = fmaf(p1,v1,O[1][1]);
            O[1][2] = fmaf(p1,v2,O[1][2]); O[1][3] = fmaf(p1,v3,O[1][3]);
            O[2][0] = fmaf(p2,v0,O[2][0]); O[2][1] = fmaf(p2,v1,O[2][1]);
            O[2][2] = fmaf(p2,v2,O[2][2]); O[2][3] = fmaf(p2,v3,O[2][3]);
            O[3][0] = fmaf(p3,v0,O[3][0]); O[3][1] = fmaf(p3,v1,O[3][1]);
            O[3][2] = fmaf(p3,v2,O[3][2]); O[3][3] = fmaf(p3,v3,O[3][3]);
        }
    }

    // normalize + write to [B,N,D] layout for the projection GEMM
#pragma unroll
    for (int i = 0; i < 4; i++) {
        float inv = 1.0f / l_i[i];
        int row = r0 + ty4 + i;
#pragma unroll
        for (int j = 0; j < 4; j++) {
            g_att[((size_t)b*NN + row)*DD + h*HD + tx4 + j] = O[i][j] * inv;
        }
    }
}

// ---------------- launcher ----------------
extern "C" void kernel_launch(void* const* d_in, const int* in_sizes, int n_in,
                              void* d_out, int out_size) {
    const float* x       = (const float*)d_in[0];
    const float* coords  = (const float*)d_in[1];
    const float* elev    = (const float*)d_in[2];
    const float* qkv_w   = (const float*)d_in[3];
    const float* qkv_b   = (const float*)d_in[4];
    const float* proj_w  = (const float*)d_in[5];
    const float* proj_b  = (const float*)d_in[6];
    const float* btab    = (const float*)d_in[7];
    const float* alpha   = (const float*)d_in[8];
    float* out = (float*)d_out;

    prep_kernel<<<(BB*NN + 255)/256, 256>>>(coords);

    qkv_gemm<<<dim3((3*DD)/128, MROWS/128), 256>>>(x, qkv_w, qkv_b);

    cudaFuncSetAttribute(attn_kernel, cudaFuncAttributeMaxDynamicSharedMemorySize,
                         ATTN_SMEM_BYTES);
    attn_kernel<<<dim3(NN/BR, HH, BB), 256, ATTN_SMEM_BYTES>>>(elev, btab, alpha);

    proj_gemm<<<dim3(DD/128, MROWS/128), 256>>>(proj_w, proj_b, out);
}

// round 3
// speedup vs baseline: 1.3425x; 1.3425x over previous
#include <cuda_runtime.h>
#include <cuda_bf16.h>
#include <math.h>
#include <stdint.h>

#define BB 4
#define NN 1024
#define DD 768
#define HH 12
#define HD 64
#define MROWS (BB*NN)          // 4096
#define KDIM 768
#define KCHUNK 64
#define NCHUNKS (KDIM/KCHUNK)  // 12

// ---------------- scratch (no allocations allowed) ----------------
__device__ float g_q[BB*HH*NN*HD];
__device__ float g_k[BB*HH*NN*HD];
__device__ float g_v[BB*HH*NN*HD];
__device__ float g_att[BB*NN*DD];
__device__ int   g_cx[BB*NN];
__device__ int   g_cy[BB*NN];

// ---------------- helpers ----------------
__device__ __forceinline__ uint32_t smem_u32(const void* p) {
    uint32_t a;
    asm("{ .reg .u64 t; cvta.to.shared.u64 t, %1; cvt.u32.u64 %0, t; }" : "=r"(a) : "l"(p));
    return a;
}

#define LDSM_X4(r0, r1, r2, r3, addr) \
    asm volatile("ldmatrix.sync.aligned.m8n8.x4.shared.b16 {%0,%1,%2,%3}, [%4];" \
        : "=r"(r0), "=r"(r1), "=r"(r2), "=r"(r3) : "r"(addr))

#define MMA16816(d, a0, a1, a2, a3, b0, b1) \
    asm volatile("mma.sync.aligned.m16n8k16.row.col.f32.bf16.bf16.f32 " \
        "{%0,%1,%2,%3}, {%4,%5,%6,%7}, {%8,%9}, {%0,%1,%2,%3};" \
        : "+f"((d)[0]), "+f"((d)[1]), "+f"((d)[2]), "+f"((d)[3]) \
        : "r"(a0), "r"(a1), "r"(a2), "r"(a3), "r"(b0), "r"(b1))

// SW128 swizzled address within a [128 rows][128 bytes] tile
__device__ __forceinline__ uint32_t swz(uint32_t base, int row, int colb) {
    uint32_t off = (uint32_t)(row * 128 + colb);
    return base + (off ^ ((off >> 3) & 0x70));
}

// fp32 -> bf16 hi/lo split of a float4 (packed as 2x bf16x2 each)
__device__ __forceinline__ void split4(float4 f, uint2& hi, uint2& lo) {
    __nv_bfloat16 hx = __float2bfloat16_rn(f.x);
    __nv_bfloat16 hy = __float2bfloat16_rn(f.y);
    __nv_bfloat16 hz = __float2bfloat16_rn(f.z);
    __nv_bfloat16 hw = __float2bfloat16_rn(f.w);
    __nv_bfloat162 h01; h01.x = hx; h01.y = hy;
    __nv_bfloat162 h23; h23.x = hz; h23.y = hw;
    hi.x = *(uint32_t*)&h01; hi.y = *(uint32_t*)&h23;
    __nv_bfloat162 l01 = __floats2bfloat162_rn(f.x - __bfloat162float(hx), f.y - __bfloat162float(hy));
    __nv_bfloat162 l23 = __floats2bfloat162_rn(f.z - __bfloat162float(hz), f.w - __bfloat162float(hw));
    lo.x = *(uint32_t*)&l01; lo.y = *(uint32_t*)&l23;
}

// ---------------- prep: integer grid coords ----------------
__global__ void prep_kernel(const float* __restrict__ coords) {
    int i = blockIdx.x * blockDim.x + threadIdx.x;
    if (i < BB*NN) {
        g_cx[i] = (int)(coords[2*i + 0] * 128.0f);
        g_cy[i] = (int)(coords[2*i + 1] * 128.0f);
    }
}

// ---------------- HMMA bf16x3 GEMM: C[M,N] = A[M,K] . B[N,K]^T + bias ----------------
// MODE 0: qkv epilogue (scatter to g_q/g_k/g_v, q scaled). MODE 1: plain store, A = g_att.
// smem: Ahi[128][64]bf16 | Alo | Bhi | Blo  (16KB each, SW128)
#define GEMM_SMEM 65536

template<int MODE>
__global__ __launch_bounds__(256) void mma_gemm(const float* __restrict__ Ain,
                                                const float* __restrict__ Bw,
                                                const float* __restrict__ bias,
                                                float* __restrict__ Cout) {
    extern __shared__ char smem[];
    const float* A = (MODE == 1) ? (const float*)g_att : Ain;
    uint32_t sb = smem_u32(smem);
    const uint32_t sAhi = sb;
    const uint32_t sAlo = sb + 16384;
    const uint32_t sBhi = sb + 32768;
    const uint32_t sBlo = sb + 49152;

    const int tid = threadIdx.x;
    const int wid = tid >> 5;
    const int lane = tid & 31;
    const int warp_m = wid >> 2;      // 0..1  (64 rows each)
    const int warp_n = wid & 3;       // 0..3  (32 cols each)
    const int row0 = blockIdx.y * 128;
    const int col0 = blockIdx.x * 128;

    float acc[4][4][4];
#pragma unroll
    for (int i = 0; i < 4; i++)
#pragma unroll
        for (int j = 0; j < 4; j++)
#pragma unroll
            for (int r = 0; r < 4; r++) acc[i][j][r] = 0.0f;

    // loader indices: 256 threads x 8 iters cover 128 rows x 16 float4
    const int lrow = tid >> 4;        // +16 per iter... no: idx layout below
    for (int ch = 0; ch < NCHUNKS; ch++) {
        const int kt0 = ch * KCHUNK;
        __syncthreads();   // previous chunk's MMAs done
#pragma unroll
        for (int it = 0; it < 8; it++) {
            int idx = it * 256 + tid;
            int row = idx >> 4;          // 0..127
            int cg  = idx & 15;          // float4 group within 64 floats
            uint32_t off = (uint32_t)(row * 128 + cg * 8);
            uint32_t sw = off ^ ((off >> 3) & 0x70);
            float4 fa = *(const float4*)(A  + (size_t)(row0 + row)*KDIM + kt0 + cg*4);
            float4 fb = *(const float4*)(Bw + (size_t)(col0 + row)*KDIM + kt0 + cg*4);
            uint2 ah, al, bh, bl;
            split4(fa, ah, al);
            split4(fb, bh, bl);
            *(uint2*)((char*)smem + (sAhi - sb) + sw) = ah;
            *(uint2*)((char*)smem + (sAlo - sb) + sw) = al;
            *(uint2*)((char*)smem + (sBhi - sb) + sw) = bh;
            *(uint2*)((char*)smem + (sBlo - sb) + sw) = bl;
        }
        __syncthreads();

#pragma unroll
        for (int ks = 0; ks < 4; ks++) {
            // B fragments: 2 ldmatrix.x4 per precision, covering 4 n8 tiles
            uint32_t bh[4][2], bl[4][2];
#pragma unroll
            for (int g = 0; g < 2; g++) {
                int brow = warp_n*32 + g*16 + (lane & 15);
                int bcol = ks*32 + ((lane >> 4) << 4);
                uint32_t r0, r1, r2, r3;
                LDSM_X4(r0, r1, r2, r3, swz(sBhi, brow, bcol));
                bh[g*2+0][0] = r0; bh[g*2+1][0] = r1;
                bh[g*2+0][1] = r2; bh[g*2+1][1] = r3;
                LDSM_X4(r0, r1, r2, r3, swz(sBlo, brow, bcol));
                bl[g*2+0][0] = r0; bl[g*2+1][0] = r1;
                bl[g*2+0][1] = r2; bl[g*2+1][1] = r3;
            }
#pragma unroll
            for (int mt = 0; mt < 4; mt++) {
                int arow = warp_m*64 + mt*16 + (lane & 15);
                int acol = ks*32 + ((lane >> 4) << 4);
                uint32_t ah0, ah1, ah2, ah3, al0, al1, al2, al3;
                LDSM_X4(ah0, ah1, ah2, ah3, swz(sAhi, arow, acol));
                LDSM_X4(al0, al1, al2, al3, swz(sAlo, arow, acol));
#pragma unroll
                for (int nt = 0; nt < 4; nt++) {
                    MMA16816(acc[mt][nt], ah0, ah1, ah2, ah3, bh[nt][0], bh[nt][1]);
                    MMA16816(acc[mt][nt], ah0, ah1, ah2, ah3, bl[nt][0], bl[nt][1]);
                    MMA16816(acc[mt][nt], al0, al1, al2, al3, bh[nt][0], bh[nt][1]);
                }
            }
        }
    }

    // epilogue: scatter register accumulators
    const int gr = lane >> 2;
    const int gc = (lane & 3) * 2;
#pragma unroll
    for (int mt = 0; mt < 4; mt++) {
#pragma unroll
        for (int nt = 0; nt < 4; nt++) {
            int m0 = row0 + warp_m*64 + mt*16 + gr;
            int jg = col0 + warp_n*32 + nt*8 + gc;
            float b0 = bias[jg], b1 = bias[jg+1];
#pragma unroll
            for (int half = 0; half < 2; half++) {
                int m = m0 + half*8;
                float c0 = acc[mt][nt][half*2+0] + b0;
                float c1 = acc[mt][nt][half*2+1] + b1;
                if (MODE == 0) {
                    int which = col0 / DD;
                    int rem = jg - which * DD;
                    int h = rem >> 6, dd0 = rem & 63;
                    int bidx = m >> 10, n = m & 1023;
                    float sc = (which == 0) ? 0.125f : 1.0f;
                    float* dst = (which == 0 ? g_q : (which == 1 ? g_k : g_v))
                                 + (((size_t)(bidx*HH + h))*NN + n)*HD + dd0;
                    float2 o = make_float2(c0 * sc, c1 * sc);
                    *(float2*)dst = o;
                } else {
                    *(float2*)(Cout + (size_t)m * DD + jg) = make_float2(c0, c1);
                }
            }
        }
    }
}

// ---------------- fused attention (flash-style, unchanged from R1) ----------------
#define BR 64
#define BC 64
#define SP 65
#define ATTN_SMEM_BYTES ((3*64*SP + 2*64) * 4 + (260 + 4*64) * 4)

__global__ __launch_bounds__(256) void attn_kernel(const float* __restrict__ elev,
                                                   const float* __restrict__ btab,
                                                   const float* __restrict__ alpha_p) {
    extern __shared__ float smf[];
    float* qs = smf;
    float* ks = qs + 64*SP;
    float* vs = ks + 64*SP;
    float* er = vs + 64*SP;
    float* ec = er + 64;
    int*   lut = (int*)(ec + 64);
    int*   cxr = lut + 260;
    int*   cyr = cxr + 64;
    int*   cxc = cyr + 64;
    int*   cyc = cxc + 64;

    int tid = threadIdx.x;
    int tx = tid & 15, ty = tid >> 4;
    int ty4 = ty * 4, tx4 = tx * 4;
    int r0 = blockIdx.x * BR;
    int h  = blockIdx.y;
    int b  = blockIdx.z;
    float alpha = alpha_p[0];

    for (int i = tid; i < 257; i += 256) {
        int rel = i - 128;
        int neg = -rel;
        int ret = (neg < 0) ? 16 : 0;
        int a = (neg < 0) ? -neg : neg;
        int bv;
        if (a < 8) bv = a;
        else {
            float t = logf((float)a * 0.125f) / 2.7725887222397811f * 8.0f;
            bv = 8 + (int)t;
            if (bv > 15) bv = 15;
        }
        lut[i] = ret + bv;
    }

    const float* qptr = g_q + (((size_t)(b*HH + h))*NN + r0)*HD;
    for (int e = tid; e < BR*HD/4; e += 256) {
        int lr = e >> 4;
        int d4 = (e & 15) << 2;
        float4 q4 = *(const float4*)(qptr + lr*HD + d4);
        qs[lr*SP + d4 + 0] = q4.x; qs[lr*SP + d4 + 1] = q4.y;
        qs[lr*SP + d4 + 2] = q4.z; qs[lr*SP + d4 + 3] = q4.w;
    }
    if (tid < 64) {
        int gr = b*NN + r0 + tid;
        cxr[tid] = g_cx[gr]; cyr[tid] = g_cy[gr]; er[tid] = elev[gr];
    }

    float m_i[4], l_i[4], O[4][4];
#pragma unroll
    for (int i = 0; i < 4; i++) {
        m_i[i] = -INFINITY; l_i[i] = 0.0f;
#pragma unroll
        for (int j = 0; j < 4; j++) O[i][j] = 0.0f;
    }

    const float* kbase = g_k + ((size_t)(b*HH + h))*NN*HD;
    const float* vbase = g_v + ((size_t)(b*HH + h))*NN*HD;

    for (int t = 0; t < NN/BC; t++) {
        int c0 = t * BC;
        __syncthreads();
        for (int e = tid; e < BC*HD/4; e += 256) {
            int lc = e >> 4;
            int d4 = (e & 15) << 2;
            float4 k4 = *(const float4*)(kbase + (size_t)(c0+lc)*HD + d4);
            ks[lc*SP + d4 + 0] = k4.x; ks[lc*SP + d4 + 1] = k4.y;
            ks[lc*SP + d4 + 2] = k4.z; ks[lc*SP + d4 + 3] = k4.w;
            float4 v4 = *(const float4*)(vbase + (size_t)(c0+lc)*HD + d4);
            vs[lc*SP + d4 + 0] = v4.x; vs[lc*SP + d4 + 1] = v4.y;
            vs[lc*SP + d4 + 2] = v4.z; vs[lc*SP + d4 + 3] = v4.w;
        }
        if (tid < 64) {
            int gc = b*NN + c0 + tid;
            cxc[tid] = g_cx[gc]; cyc[tid] = g_cy[gc]; ec[tid] = elev[gc];
        }
        __syncthreads();

        float s[4][4];
#pragma unroll
        for (int i = 0; i < 4; i++)
#pragma unroll
            for (int j = 0; j < 4; j++) s[i][j] = 0.0f;
#pragma unroll 8
        for (int d = 0; d < HD; d++) {
            float a0 = qs[(ty4+0)*SP + d];
            float a1 = qs[(ty4+1)*SP + d];
            float a2 = qs[(ty4+2)*SP + d];
            float a3 = qs[(ty4+3)*SP + d];
            float b0 = ks[(tx4+0)*SP + d];
            float b1 = ks[(tx4+1)*SP + d];
            float b2 = ks[(tx4+2)*SP + d];
            float b3 = ks[(tx4+3)*SP + d];
            s[0][0] = fmaf(a0,b0,s[0][0]); s[0][1] = fmaf(a0,b1,s[0][1]);
            s[0][2] = fmaf(a0,b2,s[0][2]); s[0][3] = fmaf(a0,b3,s[0][3]);
            s[1][0] = fmaf(a1,b0,s[1][0]); s[1][1] = fmaf(a1,b1,s[1][1]);
            s[1][2] = fmaf(a1,b2,s[1][2]); s[1][3] = fmaf(a1,b3,s[1][3]);
            s[2][0] = fmaf(a2,b0,s[2][0]); s[2][1] = fmaf(a2,b1,s[2][1]);
            s[2][2] = fmaf(a2,b2,s[2][2]); s[2][3] = fmaf(a2,b3,s[2][3]);
            s[3][0] = fmaf(a3,b0,s[3][0]); s[3][1] = fmaf(a3,b1,s[3][1]);
            s[3][2] = fmaf(a3,b2,s[3][2]); s[3][3] = fmaf(a3,b3,s[3][3]);
        }
        __syncthreads();

#pragma unroll
        for (int i = 0; i < 4; i++) {
            int lr = ty4 + i;
            int cxi = cxr[lr], cyi = cyr[lr];
            float ei = er[lr];
#pragma unroll
            for (int j = 0; j < 4; j++) {
                int lc = tx4 + j;
                int bx = lut[cxi - cxc[lc] + 128];
                int by = lut[cyi - cyc[lc] + 128];
                float rb = __ldg(btab + (bx*32 + by)*HH + h);
                float diff = (ec[lc] - ei) / 1000.0f;
                float eb = fminf(fmaxf(-alpha * fmaxf(diff, 0.0f), -10.0f), 0.0f);
                s[i][j] += rb + eb;
            }
            float rm = fmaxf(fmaxf(s[i][0], s[i][1]), fmaxf(s[i][2], s[i][3]));
#pragma unroll
            for (int off = 1; off < 16; off <<= 1)
                rm = fmaxf(rm, __shfl_xor_sync(0xffffffffu, rm, off));
            float mn = fmaxf(m_i[i], rm);
            float corr = __expf(m_i[i] - mn);
            m_i[i] = mn;
            float rs = 0.0f;
#pragma unroll
            for (int j = 0; j < 4; j++) {
                float p = __expf(s[i][j] - mn);
                s[i][j] = p;
                rs += p;
            }
#pragma unroll
            for (int off = 1; off < 16; off <<= 1)
                rs += __shfl_xor_sync(0xffffffffu, rs, off);
            l_i[i] = l_i[i] * corr + rs;
#pragma unroll
            for (int j = 0; j < 4; j++) {
                O[i][j] *= corr;
                ks[lr*SP + tx4 + j] = s[i][j];
            }
        }
        __syncthreads();

#pragma unroll 8
        for (int c = 0; c < BC; c++) {
            float p0 = ks[(ty4+0)*SP + c];
            float p1 = ks[(ty4+1)*SP + c];
            float p2 = ks[(ty4+2)*SP + c];
            float p3 = ks[(ty4+3)*SP + c];
            float v0 = vs[c*SP + tx4 + 0];
            float v1 = vs[c*SP + tx4 + 1];
            float v2 = vs[c*SP + tx4 + 2];
            float v3 = vs[c*SP + tx4 + 3];
            O[0][0] = fmaf(p0,v0,O[0][0]); O[0][1] = fmaf(p0,v1,O[0][1]);
            O[0][2] = fmaf(p0,v2,O[0][2]); O[0][3] = fmaf(p0,v3,O[0][3]);
            O[1][0] = fmaf(p1,v0,O[1][0]); O[1][1] = fmaf(p1,v1,O[1][1]);
            O[1][2] = fmaf(p1,v2,O[1][2]); O[1][3] = fmaf(p1,v3,O[1][3]);
            O[2][0] = fmaf(p2,v0,O[2][0]); O[2][1] = fmaf(p2,v1,O[2][1]);
            O[2][2] = fmaf(p2,v2,O[2][2]); O[2][3] = fmaf(p2,v3,O[2][3]);
            O[3][0] = fmaf(p3,v0,O[3][0]); O[3][1] = fmaf(p3,v1,O[3][1]);
            O[3][2] = fmaf(p3,v2,O[3][2]); O[3][3] = fmaf(p3,v3,O[3][3]);
        }
    }

#pragma unroll
    for (int i = 0; i < 4; i++) {
        float inv = 1.0f / l_i[i];
        int row = r0 + ty4 + i;
#pragma unroll
        for (int j = 0; j < 4; j++) {
            g_att[((size_t)b*NN + row)*DD + h*HD + tx4 + j] = O[i][j] * inv;
        }
    }
}

// ---------------- launcher ----------------
extern "C" void kernel_launch(void* const* d_in, const int* in_sizes, int n_in,
                              void* d_out, int out_size) {
    const float* x       = (const float*)d_in[0];
    const float* coords  = (const float*)d_in[1];
    const float* elev    = (const float*)d_in[2];
    const float* qkv_w   = (const float*)d_in[3];
    const float* qkv_b   = (const float*)d_in[4];
    const float* proj_w  = (const float*)d_in[5];
    const float* proj_b  = (const float*)d_in[6];
    const float* btab    = (const float*)d_in[7];
    const float* alpha   = (const float*)d_in[8];
    float* out = (float*)d_out;

    prep_kernel<<<(BB*NN + 255)/256, 256>>>(coords);

    cudaFuncSetAttribute(mma_gemm<0>, cudaFuncAttributeMaxDynamicSharedMemorySize, GEMM_SMEM);
    cudaFuncSetAttribute(mma_gemm<1>, cudaFuncAttributeMaxDynamicSharedMemorySize, GEMM_SMEM);

    mma_gemm<0><<<dim3((3*DD)/128, MROWS/128), 256, GEMM_SMEM>>>(x, qkv_w, qkv_b, nullptr);

    cudaFuncSetAttribute(attn_kernel, cudaFuncAttributeMaxDynamicSharedMemorySize, ATTN_SMEM_BYTES);
    attn_kernel<<<dim3(NN/BR, HH, BB), 256, ATTN_SMEM_BYTES>>>(elev, btab, alpha);

    mma_gemm<1><<<dim3(DD/128, MROWS/128), 256, GEMM_SMEM>>>(nullptr, proj_w, proj_b, out);
}

// round 4
// speedup vs baseline: 2.2219x; 1.6551x over previous
#include <cuda_runtime.h>
#include <cuda_bf16.h>
#include <math.h>
#include <stdint.h>

#define BB 4
#define NN 1024
#define DD 768
#define HH 12
#define HD 64
#define MROWS (BB*NN)          // 4096
#define KDIM 768
#define KCHUNK 64
#define NCHUNKS (KDIM/KCHUNK)  // 12

// ---------------- scratch (no allocations allowed) ----------------
__device__ __nv_bfloat16 g_qh[BB*HH*NN*HD];
__device__ __nv_bfloat16 g_ql[BB*HH*NN*HD];
__device__ __nv_bfloat16 g_kh[BB*HH*NN*HD];
__device__ __nv_bfloat16 g_kl[BB*HH*NN*HD];
__device__ __nv_bfloat16 g_vh[BB*HH*NN*HD];
__device__ __nv_bfloat16 g_vl[BB*HH*NN*HD];
__device__ float g_att[BB*NN*DD];
__device__ int   g_cx[BB*NN];
__device__ int   g_cy[BB*NN];

// ---------------- helpers ----------------
__device__ __forceinline__ uint32_t smem_u32(const void* p) {
    uint32_t a;
    asm("{ .reg .u64 t; cvta.to.shared.u64 t, %1; cvt.u32.u64 %0, t; }" : "=r"(a) : "l"(p));
    return a;
}

#define LDSM_X4(r0, r1, r2, r3, addr) \
    asm volatile("ldmatrix.sync.aligned.m8n8.x4.shared.b16 {%0,%1,%2,%3}, [%4];" \
        : "=r"(r0), "=r"(r1), "=r"(r2), "=r"(r3) : "r"(addr))

#define LDSM_X4_T(r0, r1, r2, r3, addr) \
    asm volatile("ldmatrix.sync.aligned.m8n8.x4.trans.shared.b16 {%0,%1,%2,%3}, [%4];" \
        : "=r"(r0), "=r"(r1), "=r"(r2), "=r"(r3) : "r"(addr))

#define MMA16816(d, a0, a1, a2, a3, b0, b1) \
    asm volatile("mma.sync.aligned.m16n8k16.row.col.f32.bf16.bf16.f32 " \
        "{%0,%1,%2,%3}, {%4,%5,%6,%7}, {%8,%9}, {%0,%1,%2,%3};" \
        : "+f"((d)[0]), "+f"((d)[1]), "+f"((d)[2]), "+f"((d)[3]) \
        : "r"(a0), "r"(a1), "r"(a2), "r"(a3), "r"(b0), "r"(b1))

// SW128 swizzled address within a [rows][128 bytes] tile
__device__ __forceinline__ uint32_t swz(uint32_t base, int row, int colb) {
    uint32_t off = (uint32_t)(row * 128 + colb);
    return base + (off ^ ((off >> 3) & 0x70));
}

// fp32 -> bf16 hi/lo split of a float4 (packed as 2x bf16x2 each)
__device__ __forceinline__ void split4(float4 f, uint2& hi, uint2& lo) {
    __nv_bfloat16 hx = __float2bfloat16_rn(f.x);
    __nv_bfloat16 hy = __float2bfloat16_rn(f.y);
    __nv_bfloat16 hz = __float2bfloat16_rn(f.z);
    __nv_bfloat16 hw = __float2bfloat16_rn(f.w);
    __nv_bfloat162 h01; h01.x = hx; h01.y = hy;
    __nv_bfloat162 h23; h23.x = hz; h23.y = hw;
    hi.x = *(uint32_t*)&h01; hi.y = *(uint32_t*)&h23;
    __nv_bfloat162 l01 = __floats2bfloat162_rn(f.x - __bfloat162float(hx), f.y - __bfloat162float(hy));
    __nv_bfloat162 l23 = __floats2bfloat162_rn(f.z - __bfloat162float(hz), f.w - __bfloat162float(hw));
    lo.x = *(uint32_t*)&l01; lo.y = *(uint32_t*)&l23;
}

__device__ __forceinline__ uint32_t pack_hi(float a, float b) {
    __nv_bfloat162 h = __floats2bfloat162_rn(a, b);
    return *(uint32_t*)&h;
}
__device__ __forceinline__ uint32_t pack_lo(float a, float b) {
    __nv_bfloat16 ha = __float2bfloat16_rn(a);
    __nv_bfloat16 hb = __float2bfloat16_rn(b);
    __nv_bfloat162 l = __floats2bfloat162_rn(a - __bfloat162float(ha), b - __bfloat162float(hb));
    return *(uint32_t*)&l;
}

// ---------------- prep: integer grid coords ----------------
__global__ void prep_kernel(const float* __restrict__ coords) {
    int i = blockIdx.x * blockDim.x + threadIdx.x;
    if (i < BB*NN) {
        g_cx[i] = (int)(coords[2*i + 0] * 128.0f);
        g_cy[i] = (int)(coords[2*i + 1] * 128.0f);
    }
}

// ---------------- HMMA bf16x3 GEMM: C[M,N] = A[M,K] . B[N,K]^T + bias ----------------
// MODE 0: qkv epilogue (bf16 hi/lo scatter to g_q*/g_k*/g_v*, q scaled). MODE 1: float store, A = g_att.
#define GEMM_SMEM 65536

template<int MODE>
__global__ __launch_bounds__(256) void mma_gemm(const float* __restrict__ Ain,
                                                const float* __restrict__ Bw,
                                                const float* __restrict__ bias,
                                                float* __restrict__ Cout) {
    extern __shared__ char smem[];
    const float* A = (MODE == 1) ? (const float*)g_att : Ain;
    uint32_t sb = smem_u32(smem);
    const uint32_t sAhi = sb;
    const uint32_t sAlo = sb + 16384;
    const uint32_t sBhi = sb + 32768;
    const uint32_t sBlo = sb + 49152;

    const int tid = threadIdx.x;
    const int wid = tid >> 5;
    const int lane = tid & 31;
    const int warp_m = wid >> 2;
    const int warp_n = wid & 3;
    const int row0 = blockIdx.y * 128;
    const int col0 = blockIdx.x * 128;

    float acc[4][4][4];
#pragma unroll
    for (int i = 0; i < 4; i++)
#pragma unroll
        for (int j = 0; j < 4; j++)
#pragma unroll
            for (int r = 0; r < 4; r++) acc[i][j][r] = 0.0f;

    for (int ch = 0; ch < NCHUNKS; ch++) {
        const int kt0 = ch * KCHUNK;
        __syncthreads();
#pragma unroll
        for (int it = 0; it < 8; it++) {
            int idx = it * 256 + tid;
            int row = idx >> 4;
            int cg  = idx & 15;
            uint32_t off = (uint32_t)(row * 128 + cg * 8);
            uint32_t sw = off ^ ((off >> 3) & 0x70);
            float4 fa = *(const float4*)(A  + (size_t)(row0 + row)*KDIM + kt0 + cg*4);
            float4 fb = *(const float4*)(Bw + (size_t)(col0 + row)*KDIM + kt0 + cg*4);
            uint2 ah, al, bh, bl;
            split4(fa, ah, al);
            split4(fb, bh, bl);
            *(uint2*)((char*)smem + (sAhi - sb) + sw) = ah;
            *(uint2*)((char*)smem + (sAlo - sb) + sw) = al;
            *(uint2*)((char*)smem + (sBhi - sb) + sw) = bh;
            *(uint2*)((char*)smem + (sBlo - sb) + sw) = bl;
        }
        __syncthreads();

#pragma unroll
        for (int ks = 0; ks < 4; ks++) {
            uint32_t bh[4][2], bl[4][2];
#pragma unroll
            for (int g = 0; g < 2; g++) {
                int brow = warp_n*32 + g*16 + (lane & 15);
                int bcol = ks*32 + ((lane >> 4) << 4);
                uint32_t r0, r1, r2, r3;
                LDSM_X4(r0, r1, r2, r3, swz(sBhi, brow, bcol));
                bh[g*2+0][0] = r0; bh[g*2+1][0] = r1;
                bh[g*2+0][1] = r2; bh[g*2+1][1] = r3;
                LDSM_X4(r0, r1, r2, r3, swz(sBlo, brow, bcol));
                bl[g*2+0][0] = r0; bl[g*2+1][0] = r1;
                bl[g*2+0][1] = r2; bl[g*2+1][1] = r3;
            }
#pragma unroll
            for (int mt = 0; mt < 4; mt++) {
                int arow = warp_m*64 + mt*16 + (lane & 15);
                int acol = ks*32 + ((lane >> 4) << 4);
                uint32_t ah0, ah1, ah2, ah3, al0, al1, al2, al3;
                LDSM_X4(ah0, ah1, ah2, ah3, swz(sAhi, arow, acol));
                LDSM_X4(al0, al1, al2, al3, swz(sAlo, arow, acol));
#pragma unroll
                for (int nt = 0; nt < 4; nt++) {
                    MMA16816(acc[mt][nt], ah0, ah1, ah2, ah3, bh[nt][0], bh[nt][1]);
                    MMA16816(acc[mt][nt], ah0, ah1, ah2, ah3, bl[nt][0], bl[nt][1]);
                    MMA16816(acc[mt][nt], al0, al1, al2, al3, bh[nt][0], bh[nt][1]);
                }
            }
        }
    }

    const int gr = lane >> 2;
    const int gc = (lane & 3) * 2;
#pragma unroll
    for (int mt = 0; mt < 4; mt++) {
#pragma unroll
        for (int nt = 0; nt < 4; nt++) {
            int m0 = row0 + warp_m*64 + mt*16 + gr;
            int jg = col0 + warp_n*32 + nt*8 + gc;
            float b0 = bias[jg], b1 = bias[jg+1];
#pragma unroll
            for (int half = 0; half < 2; half++) {
                int m = m0 + half*8;
                float c0 = acc[mt][nt][half*2+0] + b0;
                float c1 = acc[mt][nt][half*2+1] + b1;
                if (MODE == 0) {
                    int which = col0 / DD;
                    int rem = jg - which * DD;
                    int h = rem >> 6, dd0 = rem & 63;
                    int bidx = m >> 10, n = m & 1023;
                    float sc = (which == 0) ? 0.125f : 1.0f;
                    c0 *= sc; c1 *= sc;
                    size_t off = (((size_t)(bidx*HH + h))*NN + n)*HD + dd0;
                    __nv_bfloat16* dh = (which == 0 ? g_qh : (which == 1 ? g_kh : g_vh)) + off;
                    __nv_bfloat16* dl = (which == 0 ? g_ql : (which == 1 ? g_kl : g_vl)) + off;
                    __nv_bfloat16 h0 = __float2bfloat16_rn(c0);
                    __nv_bfloat16 h1 = __float2bfloat16_rn(c1);
                    __nv_bfloat162 hh; hh.x = h0; hh.y = h1;
                    __nv_bfloat162 ll = __floats2bfloat162_rn(c0 - __bfloat162float(h0),
                                                              c1 - __bfloat162float(h1));
                    *(__nv_bfloat162*)dh = hh;
                    *(__nv_bfloat162*)dl = ll;
                } else {
                    *(float2*)(Cout + (size_t)m * DD + jg) = make_float2(c0, c1);
                }
            }
        }
    }
}

// ---------------- HMMA flash attention ----------------
// BR=128 rows per CTA, BC=64 cols per tile, 8 warps (16 rows each).
// smem: Qh(16K) Ql(16K) Kh(8K) Kl(8K) Vh(8K) Vl(8K) = 64KB + meta
#define A2_QH 0
#define A2_QL 16384
#define A2_KH 32768
#define A2_KL 40960
#define A2_VH 49152
#define A2_VL 57344
#define A2_META 65536
// meta: er[128]f ec[64]f cxr[128] cyr[128] cxc[64] cyc[64] lut[257]
#define ATTN2_SMEM (65536 + (128+64)*4 + (128+128+64+64+257)*4)

__global__ __launch_bounds__(256) void attn_mma(const float* __restrict__ elev,
                                                const float* __restrict__ btab,
                                                const float* __restrict__ alpha_p) {
    extern __shared__ char sm[];
    uint32_t sb = smem_u32(sm);
    float* er  = (float*)(sm + A2_META);
    float* ec  = er + 128;
    int* cxr   = (int*)(ec + 64);
    int* cyr   = cxr + 128;
    int* cxc   = cyr + 128;
    int* cyc   = cxc + 64;
    int* lut   = cyc + 64;

    const int tid = threadIdx.x;
    const int wid = tid >> 5;
    const int lane = tid & 31;
    const int gr = lane >> 2;
    const int q2 = (lane & 3) * 2;
    const int r0 = blockIdx.x * 128;
    const int h  = blockIdx.y;
    const int b  = blockIdx.z;
    const float alpha = alpha_p[0];

    // bucket LUT
    for (int i = tid; i < 257; i += 256) {
        int rel = i - 128;
        int neg = -rel;
        int ret = (neg < 0) ? 16 : 0;
        int a = (neg < 0) ? -neg : neg;
        int bv;
        if (a < 8) bv = a;
        else {
            float t = logf((float)a * 0.125f) / 2.7725887222397811f * 8.0f;
            bv = 8 + (int)t;
            if (bv > 15) bv = 15;
        }
        lut[i] = ret + bv;
    }

    // load Q (hi/lo) into smem + row metadata
    const size_t qbase = (((size_t)(b*HH + h))*NN + r0)*HD;
#pragma unroll
    for (int it = 0; it < 4; it++) {
        int idx = it*256 + tid;
        int row = idx >> 3;
        int cg  = idx & 7;
        uint32_t off = (uint32_t)(row*128 + cg*16);
        uint32_t sw = off ^ ((off >> 3) & 0x70);
        *(uint4*)(sm + A2_QH + sw) = *(const uint4*)(g_qh + qbase + (size_t)row*HD + cg*8);
        *(uint4*)(sm + A2_QL + sw) = *(const uint4*)(g_ql + qbase + (size_t)row*HD + cg*8);
    }
    if (tid < 128) {
        int gidx = b*NN + r0 + tid;
        cxr[tid] = g_cx[gidx]; cyr[tid] = g_cy[gidx]; er[tid] = elev[gidx];
    }

    float m_i[2], l_i[2], oacc[8][4];
#pragma unroll
    for (int rr = 0; rr < 2; rr++) { m_i[rr] = -INFINITY; l_i[rr] = 0.0f; }
#pragma unroll
    for (int dt = 0; dt < 8; dt++)
#pragma unroll
        for (int r = 0; r < 4; r++) oacc[dt][r] = 0.0f;

    const size_t kvbase = ((size_t)(b*HH + h))*NN*HD;

    for (int t = 0; t < NN/64; t++) {
        const int c0 = t*64;
        __syncthreads();
#pragma unroll
        for (int it = 0; it < 2; it++) {
            int idx = it*256 + tid;
            int row = idx >> 3;
            int cg  = idx & 7;
            uint32_t off = (uint32_t)(row*128 + cg*16);
            uint32_t sw = off ^ ((off >> 3) & 0x70);
            size_t g = kvbase + (size_t)(c0 + row)*HD + cg*8;
            *(uint4*)(sm + A2_KH + sw) = *(const uint4*)(g_kh + g);
            *(uint4*)(sm + A2_KL + sw) = *(const uint4*)(g_kl + g);
            *(uint4*)(sm + A2_VH + sw) = *(const uint4*)(g_vh + g);
            *(uint4*)(sm + A2_VL + sw) = *(const uint4*)(g_vl + g);
        }
        if (tid < 64) {
            int gidx = b*NN + c0 + tid;
            cxc[tid] = g_cx[gidx]; cyc[tid] = g_cy[gidx]; ec[tid] = elev[gidx];
        }
        __syncthreads();

        // ---- S = Q K^T ----
        float sacc[8][4];
#pragma unroll
        for (int nt = 0; nt < 8; nt++)
#pragma unroll
            for (int r = 0; r < 4; r++) sacc[nt][r] = 0.0f;

#pragma unroll
        for (int ks = 0; ks < 4; ks++) {
            int arow = wid*16 + (lane & 15);
            int acol = ks*32 + ((lane >> 4) << 4);
            uint32_t ah0, ah1, ah2, ah3, al0, al1, al2, al3;
            LDSM_X4(ah0, ah1, ah2, ah3, swz(sb + A2_QH, arow, acol));
            LDSM_X4(al0, al1, al2, al3, swz(sb + A2_QL, arow, acol));
#pragma unroll
            for (int g = 0; g < 4; g++) {
                int brow = g*16 + (lane & 15);
                int bcol = ks*32 + ((lane >> 4) << 4);
                uint32_t kh0, kh1, kh2, kh3, kl0, kl1, kl2, kl3;
                LDSM_X4(kh0, kh1, kh2, kh3, swz(sb + A2_KH, brow, bcol));
                LDSM_X4(kl0, kl1, kl2, kl3, swz(sb + A2_KL, brow, bcol));
                MMA16816(sacc[g*2+0], ah0, ah1, ah2, ah3, kh0, kh2);
                MMA16816(sacc[g*2+0], ah0, ah1, ah2, ah3, kl0, kl2);
                MMA16816(sacc[g*2+0], al0, al1, al2, al3, kh0, kh2);
                MMA16816(sacc[g*2+1], ah0, ah1, ah2, ah3, kh1, kh3);
                MMA16816(sacc[g*2+1], ah0, ah1, ah2, ah3, kl1, kl3);
                MMA16816(sacc[g*2+1], al0, al1, al2, al3, kh1, kh3);
            }
        }

        // ---- biases + online softmax ----
#pragma unroll
        for (int rr = 0; rr < 2; rr++) {
            int lrow = wid*16 + gr + rr*8;
            int cxi = cxr[lrow], cyi = cyr[lrow];
            float ei = er[lrow];
            float rm = -INFINITY;
#pragma unroll
            for (int nt = 0; nt < 8; nt++) {
#pragma unroll
                for (int e = 0; e < 2; e++) {
                    int lc = nt*8 + q2 + e;
                    int bx = lut[cxi - cxc[lc] + 128];
                    int by = lut[cyi - cyc[lc] + 128];
                    float rb = __ldg(btab + (bx*32 + by)*HH + h);
                    float diff = (ec[lc] - ei) * 0.001f;
                    float eb = fminf(fmaxf(-alpha * fmaxf(diff, 0.0f), -10.0f), 0.0f);
                    float s = sacc[nt][rr*2 + e] + rb + eb;
                    sacc[nt][rr*2 + e] = s;
                    rm = fmaxf(rm, s);
                }
            }
            rm = fmaxf(rm, __shfl_xor_sync(0xffffffffu, rm, 1));
            rm = fmaxf(rm, __shfl_xor_sync(0xffffffffu, rm, 2));
            float mn = fmaxf(m_i[rr], rm);
            float corr = __expf(m_i[rr] - mn);
            m_i[rr] = mn;
            float rs = 0.0f;
#pragma unroll
            for (int nt = 0; nt < 8; nt++) {
#pragma unroll
                for (int e = 0; e < 2; e++) {
                    float p = __expf(sacc[nt][rr*2 + e] - mn);
                    sacc[nt][rr*2 + e] = p;
                    rs += p;
                }
            }
            rs += __shfl_xor_sync(0xffffffffu, rs, 1);
            rs += __shfl_xor_sync(0xffffffffu, rs, 2);
            l_i[rr] = l_i[rr] * corr + rs;
#pragma unroll
            for (int dt = 0; dt < 8; dt++) {
                oacc[dt][rr*2 + 0] *= corr;
                oacc[dt][rr*2 + 1] *= corr;
            }
        }

        // ---- O += P V ----
#pragma unroll
        for (int kc = 0; kc < 4; kc++) {
            uint32_t pah0 = pack_hi(sacc[2*kc][0],   sacc[2*kc][1]);
            uint32_t pah1 = pack_hi(sacc[2*kc][2],   sacc[2*kc][3]);
            uint32_t pah2 = pack_hi(sacc[2*kc+1][0], sacc[2*kc+1][1]);
            uint32_t pah3 = pack_hi(sacc[2*kc+1][2], sacc[2*kc+1][3]);
            uint32_t pal0 = pack_lo(sacc[2*kc][0],   sacc[2*kc][1]);
            uint32_t pal1 = pack_lo(sacc[2*kc][2],   sacc[2*kc][3]);
            uint32_t pal2 = pack_lo(sacc[2*kc+1][0], sacc[2*kc+1][1]);
            uint32_t pal3 = pack_lo(sacc[2*kc+1][2], sacc[2*kc+1][3]);
#pragma unroll
            for (int dp = 0; dp < 4; dp++) {
                int vrow = kc*16 + (lane & 15);
                int vcol = dp*32 + ((lane >> 4) << 4);
                uint32_t vh0, vh1, vh2, vh3, vl0, vl1, vl2, vl3;
                LDSM_X4_T(vh0, vh1, vh2, vh3, swz(sb + A2_VH, vrow, vcol));
                LDSM_X4_T(vl0, vl1, vl2, vl3, swz(sb + A2_VL, vrow, vcol));
                MMA16816(oacc[dp*2+0], pah0, pah1, pah2, pah3, vh0, vh1);
                MMA16816(oacc[dp*2+0], pah0, pah1, pah2, pah3, vl0, vl1);
                MMA16816(oacc[dp*2+0], pal0, pal1, pal2, pal3, vh0, vh1);
                MMA16816(oacc[dp*2+1], pah0, pah1, pah2, pah3, vh2, vh3);
                MMA16816(oacc[dp*2+1], pah0, pah1, pah2, pah3, vl2, vl3);
                MMA16816(oacc[dp*2+1], pal0, pal1, pal2, pal3, vh2, vh3);
            }
        }
    }

    // ---- normalize + write [B,N,D] ----
#pragma unroll
    for (int rr = 0; rr < 2; rr++) {
        float inv = 1.0f / l_i[rr];
        int row = r0 + wid*16 + gr + rr*8;
#pragma unroll
        for (int dt = 0; dt < 8; dt++) {
            float2 o = make_float2(oacc[dt][rr*2+0] * inv, oacc[dt][rr*2+1] * inv);
            *(float2*)(g_att + ((size_t)b*NN + row)*DD + h*HD + dt*8 + q2) = o;
        }
    }
}

// ---------------- launcher ----------------
extern "C" void kernel_launch(void* const* d_in, const int* in_sizes, int n_in,
                              void* d_out, int out_size) {
    const float* x       = (const float*)d_in[0];
    const float* coords  = (const float*)d_in[1];
    const float* elev    = (const float*)d_in[2];
    const float* qkv_w   = (const float*)d_in[3];
    const float* qkv_b   = (const float*)d_in[4];
    const float* proj_w  = (const float*)d_in[5];
    const float* proj_b  = (const float*)d_in[6];
    const float* btab    = (const float*)d_in[7];
    const float* alpha   = (const float*)d_in[8];
    float* out = (float*)d_out;

    prep_kernel<<<(BB*NN + 255)/256, 256>>>(coords);

    cudaFuncSetAttribute(mma_gemm<0>, cudaFuncAttributeMaxDynamicSharedMemorySize, GEMM_SMEM);
    cudaFuncSetAttribute(mma_gemm<1>, cudaFuncAttributeMaxDynamicSharedMemorySize, GEMM_SMEM);
    cudaFuncSetAttribute(attn_mma, cudaFuncAttributeMaxDynamicSharedMemorySize, ATTN2_SMEM);

    mma_gemm<0><<<dim3((3*DD)/128, MROWS/128), 256, GEMM_SMEM>>>(x, qkv_w, qkv_b, nullptr);

    attn_mma<<<dim3(NN/128, HH, BB), 256, ATTN2_SMEM>>>(elev, btab, alpha);

    mma_gemm<1><<<dim3(DD/128, MROWS/128), 256, GEMM_SMEM>>>(nullptr, proj_w, proj_b, out);
}

// round 5
// speedup vs baseline: 2.4705x; 1.1119x over previous
#include <cuda_runtime.h>
#include <cuda_bf16.h>
#include <math.h>
#include <stdint.h>

#define BB 4
#define NN 1024
#define DD 768
#define HH 12
#define HD 64
#define MROWS (BB*NN)          // 4096
#define KDIM 768
#define KCHUNK 64
#define NCHUNKS (KDIM/KCHUNK)  // 12

// ---------------- scratch (no allocations allowed) ----------------
__device__ __nv_bfloat16 g_qh[BB*HH*NN*HD];
__device__ __nv_bfloat16 g_ql[BB*HH*NN*HD];
__device__ __nv_bfloat16 g_kh[BB*HH*NN*HD];
__device__ __nv_bfloat16 g_kl[BB*HH*NN*HD];
__device__ __nv_bfloat16 g_vh[BB*HH*NN*HD];
__device__ __nv_bfloat16 g_vl[BB*HH*NN*HD];
__device__ __nv_bfloat16 g_xh[MROWS*KDIM];
__device__ __nv_bfloat16 g_xl[MROWS*KDIM];
__device__ __nv_bfloat16 g_wqh[3*DD*KDIM];
__device__ __nv_bfloat16 g_wql[3*DD*KDIM];
__device__ __nv_bfloat16 g_wph[DD*KDIM];
__device__ __nv_bfloat16 g_wpl[DD*KDIM];
__device__ __nv_bfloat16 g_atth[BB*NN*DD];
__device__ __nv_bfloat16 g_attl[BB*NN*DD];
__device__ int   g_cx[BB*NN];
__device__ int   g_cy[BB*NN];

// ---------------- helpers ----------------
__device__ __forceinline__ uint32_t smem_u32(const void* p) {
    uint32_t a;
    asm("{ .reg .u64 t; cvta.to.shared.u64 t, %1; cvt.u32.u64 %0, t; }" : "=r"(a) : "l"(p));
    return a;
}

#define LDSM_X4(r0, r1, r2, r3, addr) \
    asm volatile("ldmatrix.sync.aligned.m8n8.x4.shared.b16 {%0,%1,%2,%3}, [%4];" \
        : "=r"(r0), "=r"(r1), "=r"(r2), "=r"(r3) : "r"(addr))

#define LDSM_X4_T(r0, r1, r2, r3, addr) \
    asm volatile("ldmatrix.sync.aligned.m8n8.x4.trans.shared.b16 {%0,%1,%2,%3}, [%4];" \
        : "=r"(r0), "=r"(r1), "=r"(r2), "=r"(r3) : "r"(addr))

#define MMA16816(d, a0, a1, a2, a3, b0, b1) \
    asm volatile("mma.sync.aligned.m16n8k16.row.col.f32.bf16.bf16.f32 " \
        "{%0,%1,%2,%3}, {%4,%5,%6,%7}, {%8,%9}, {%0,%1,%2,%3};" \
        : "+f"((d)[0]), "+f"((d)[1]), "+f"((d)[2]), "+f"((d)[3]) \
        : "r"(a0), "r"(a1), "r"(a2), "r"(a3), "r"(b0), "r"(b1))

#define CP_ASYNC16(dst, src) \
    asm volatile("cp.async.cg.shared.global [%0], [%1], 16;" :: "r"(dst), "l"(src) : "memory")
#define CP_COMMIT() asm volatile("cp.async.commit_group;" ::: "memory")
#define CP_WAIT(n)  asm volatile("cp.async.wait_group %0;" :: "n"(n) : "memory")

// SW128 swizzled address within a [rows][128 bytes] tile
__device__ __forceinline__ uint32_t swz(uint32_t base, int row, int colb) {
    uint32_t off = (uint32_t)(row * 128 + colb);
    return base + (off ^ ((off >> 3) & 0x70));
}

// fp32 -> bf16 hi/lo split of a float4 (packed as 2x bf16x2 each)
__device__ __forceinline__ void split4(float4 f, uint2& hi, uint2& lo) {
    __nv_bfloat16 hx = __float2bfloat16_rn(f.x);
    __nv_bfloat16 hy = __float2bfloat16_rn(f.y);
    __nv_bfloat16 hz = __float2bfloat16_rn(f.z);
    __nv_bfloat16 hw = __float2bfloat16_rn(f.w);
    __nv_bfloat162 h01; h01.x = hx; h01.y = hy;
    __nv_bfloat162 h23; h23.x = hz; h23.y = hw;
    hi.x = *(uint32_t*)&h01; hi.y = *(uint32_t*)&h23;
    __nv_bfloat162 l01 = __floats2bfloat162_rn(f.x - __bfloat162float(hx), f.y - __bfloat162float(hy));
    __nv_bfloat162 l23 = __floats2bfloat162_rn(f.z - __bfloat162float(hz), f.w - __bfloat162float(hw));
    lo.x = *(uint32_t*)&l01; lo.y = *(uint32_t*)&l23;
}

__device__ __forceinline__ uint32_t pack_hi(float a, float b) {
    __nv_bfloat162 h = __floats2bfloat162_rn(a, b);
    return *(uint32_t*)&h;
}
__device__ __forceinline__ uint32_t pack_lo(float a, float b) {
    __nv_bfloat16 ha = __float2bfloat16_rn(a);
    __nv_bfloat16 hb = __float2bfloat16_rn(b);
    __nv_bfloat162 l = __floats2bfloat162_rn(a - __bfloat162float(ha), b - __bfloat162float(hb));
    return *(uint32_t*)&l;
}

// ---------------- prep: integer grid coords ----------------
__global__ void prep_kernel(const float* __restrict__ coords) {
    int i = blockIdx.x * blockDim.x + threadIdx.x;
    if (i < BB*NN) {
        g_cx[i] = (int)(coords[2*i + 0] * 128.0f);
        g_cy[i] = (int)(coords[2*i + 1] * 128.0f);
    }
}

// ---------------- split: fp32 -> bf16 hi/lo ----------------
__global__ void split_kernel(const float* __restrict__ src,
                             __nv_bfloat16* __restrict__ h,
                             __nv_bfloat16* __restrict__ l, int n) {
    int i = (blockIdx.x * blockDim.x + threadIdx.x) * 4;
    if (i < n) {
        float4 f = *(const float4*)(src + i);
        uint2 hh, ll;
        split4(f, hh, ll);
        *(uint2*)(h + i) = hh;
        *(uint2*)(l + i) = ll;
    }
}

// ---------------- HMMA bf16x3 GEMM, cp.async 3-stage pipeline ----------------
// C[M,N] = A[M,K].B[N,K]^T + bias.  A,B pre-split bf16 hi/lo.
// MODE 0: qkv epilogue (bf16 hi/lo scatter to g_q*/g_k*/g_v*, q scaled). MODE 1: float store.
#define GSTAGES 3
#define GSTAGE_BYTES 65536
#define GEMM_SMEM (GSTAGES*GSTAGE_BYTES)   // 192KB

__device__ __forceinline__ void gemm_load_stage(uint32_t sbase,
    const __nv_bfloat16* __restrict__ Ah, const __nv_bfloat16* __restrict__ Al,
    const __nv_bfloat16* __restrict__ Bh, const __nv_bfloat16* __restrict__ Bl,
    int row0, int col0, int kt0, int tid) {
#pragma unroll
    for (int i = 0; i < 4; i++) {
        int c = i*256 + tid;
        int row = c >> 3, c16 = c & 7;
        uint32_t off = (uint32_t)(row*128 + c16*16);
        uint32_t sw = off ^ ((off >> 3) & 0x70);
        size_t ga = (size_t)(row0 + row)*KDIM + kt0 + c16*8;
        size_t gb = (size_t)(col0 + row)*KDIM + kt0 + c16*8;
        CP_ASYNC16(sbase + sw,         Ah + ga);
        CP_ASYNC16(sbase + 16384 + sw, Al + ga);
        CP_ASYNC16(sbase + 32768 + sw, Bh + gb);
        CP_ASYNC16(sbase + 49152 + sw, Bl + gb);
    }
}

template<int MODE>
__global__ __launch_bounds__(256) void mma_gemm(
        const __nv_bfloat16* __restrict__ Ah, const __nv_bfloat16* __restrict__ Al,
        const __nv_bfloat16* __restrict__ Bh, const __nv_bfloat16* __restrict__ Bl,
        const float* __restrict__ bias, float* __restrict__ Cout) {
    extern __shared__ char smem[];
    uint32_t sb = smem_u32(smem);

    const int tid = threadIdx.x;
    const int wid = tid >> 5;
    const int lane = tid & 31;
    const int warp_m = wid >> 2;
    const int warp_n = wid & 3;
    const int row0 = blockIdx.y * 128;
    const int col0 = blockIdx.x * 128;

    float acc[4][4][4];
#pragma unroll
    for (int i = 0; i < 4; i++)
#pragma unroll
        for (int j = 0; j < 4; j++)
#pragma unroll
            for (int r = 0; r < 4; r++) acc[i][j][r] = 0.0f;

    // prologue: stages 0,1
    gemm_load_stage(sb, Ah, Al, Bh, Bl, row0, col0, 0, tid);
    CP_COMMIT();
    gemm_load_stage(sb + GSTAGE_BYTES, Ah, Al, Bh, Bl, row0, col0, KCHUNK, tid);
    CP_COMMIT();

    for (int ch = 0; ch < NCHUNKS; ch++) {
        __syncthreads();   // protect stage being overwritten (computed at ch-1)
        if (ch + 2 < NCHUNKS) {
            gemm_load_stage(sb + ((ch+2)%GSTAGES)*GSTAGE_BYTES, Ah, Al, Bh, Bl,
                            row0, col0, (ch+2)*KCHUNK, tid);
            CP_COMMIT();
        }
        if (ch < NCHUNKS-2)      CP_WAIT(2);
        else if (ch == NCHUNKS-2) CP_WAIT(1);
        else                      CP_WAIT(0);
        __syncthreads();

        const uint32_t st = sb + (ch % GSTAGES)*GSTAGE_BYTES;
        const uint32_t sAhi = st, sAlo = st + 16384, sBhi = st + 32768, sBlo = st + 49152;
#pragma unroll
        for (int ks = 0; ks < 4; ks++) {
            uint32_t bh[4][2], bl[4][2];
#pragma unroll
            for (int g = 0; g < 2; g++) {
                int brow = warp_n*32 + g*16 + (lane & 15);
                int bcol = ks*32 + ((lane >> 4) << 4);
                uint32_t r0, r1, r2, r3;
                LDSM_X4(r0, r1, r2, r3, swz(sBhi, brow, bcol));
                bh[g*2+0][0] = r0; bh[g*2+1][0] = r1;
                bh[g*2+0][1] = r2; bh[g*2+1][1] = r3;
                LDSM_X4(r0, r1, r2, r3, swz(sBlo, brow, bcol));
                bl[g*2+0][0] = r0; bl[g*2+1][0] = r1;
                bl[g*2+0][1] = r2; bl[g*2+1][1] = r3;
            }
#pragma unroll
            for (int mt = 0; mt < 4; mt++) {
                int arow = warp_m*64 + mt*16 + (lane & 15);
                int acol = ks*32 + ((lane >> 4) << 4);
                uint32_t ah0, ah1, ah2, ah3, al0, al1, al2, al3;
                LDSM_X4(ah0, ah1, ah2, ah3, swz(sAhi, arow, acol));
                LDSM_X4(al0, al1, al2, al3, swz(sAlo, arow, acol));
#pragma unroll
                for (int nt = 0; nt < 4; nt++) {
                    MMA16816(acc[mt][nt], ah0, ah1, ah2, ah3, bh[nt][0], bh[nt][1]);
                    MMA16816(acc[mt][nt], ah0, ah1, ah2, ah3, bl[nt][0], bl[nt][1]);
                    MMA16816(acc[mt][nt], al0, al1, al2, al3, bh[nt][0], bh[nt][1]);
                }
            }
        }
    }

    const int gr = lane >> 2;
    const int gc = (lane & 3) * 2;
#pragma unroll
    for (int mt = 0; mt < 4; mt++) {
#pragma unroll
        for (int nt = 0; nt < 4; nt++) {
            int m0 = row0 + warp_m*64 + mt*16 + gr;
            int jg = col0 + warp_n*32 + nt*8 + gc;
            float b0 = bias[jg], b1 = bias[jg+1];
#pragma unroll
            for (int half = 0; half < 2; half++) {
                int m = m0 + half*8;
                float c0 = acc[mt][nt][half*2+0] + b0;
                float c1 = acc[mt][nt][half*2+1] + b1;
                if (MODE == 0) {
                    int which = col0 / DD;
                    int rem = jg - which * DD;
                    int h = rem >> 6, dd0 = rem & 63;
                    int bidx = m >> 10, n = m & 1023;
                    float sc = (which == 0) ? 0.125f : 1.0f;
                    c0 *= sc; c1 *= sc;
                    size_t off = (((size_t)(bidx*HH + h))*NN + n)*HD + dd0;
                    __nv_bfloat16* dh = (which == 0 ? g_qh : (which == 1 ? g_kh : g_vh)) + off;
                    __nv_bfloat16* dl = (which == 0 ? g_ql : (which == 1 ? g_kl : g_vl)) + off;
                    __nv_bfloat16 h0 = __float2bfloat16_rn(c0);
                    __nv_bfloat16 h1 = __float2bfloat16_rn(c1);
                    __nv_bfloat162 hh; hh.x = h0; hh.y = h1;
                    __nv_bfloat162 ll = __floats2bfloat162_rn(c0 - __bfloat162float(h0),
                                                              c1 - __bfloat162float(h1));
                    *(__nv_bfloat162*)dh = hh;
                    *(__nv_bfloat162*)dl = ll;
                } else {
                    *(float2*)(Cout + (size_t)m * DD + jg) = make_float2(c0, c1);
                }
            }
        }
    }
}

// ---------------- HMMA flash attention, cp.async 2-stage K/V pipeline ----------------
// BR=128 rows per CTA, BC=64 cols per tile, 8 warps (16 rows each).
#define A2_QH 0
#define A2_QL 16384
#define A2_KV 32768
#define KV_STAGE 32768     // KH 8K | KL 8K | VH 8K | VL 8K
#define A2_META (A2_KV + 2*KV_STAGE)   // 98304
#define ATTN2_SMEM (A2_META + (128+64)*4 + (128+128+64+64+257)*4)

__device__ __forceinline__ void attn_load_kv(uint32_t sbase, size_t kvbase, int c0, int tid) {
#pragma unroll
    for (int i = 0; i < 2; i++) {
        int c = i*256 + tid;          // 0..511
        int row = c >> 3, c16 = c & 7;
        uint32_t off = (uint32_t)(row*128 + c16*16);
        uint32_t sw = off ^ ((off >> 3) & 0x70);
        size_t g = kvbase + (size_t)(c0 + row)*HD + c16*8;
        CP_ASYNC16(sbase + sw,         g_kh + g);
        CP_ASYNC16(sbase + 8192 + sw,  g_kl + g);
        CP_ASYNC16(sbase + 16384 + sw, g_vh + g);
        CP_ASYNC16(sbase + 24576 + sw, g_vl + g);
    }
}

__global__ __launch_bounds__(256) void attn_mma(const float* __restrict__ elev,
                                                const float* __restrict__ btab,
                                                const float* __restrict__ alpha_p) {
    extern __shared__ char sm[];
    uint32_t sb = smem_u32(sm);
    float* er  = (float*)(sm + A2_META);
    float* ec  = er + 128;
    int* cxr   = (int*)(ec + 64);
    int* cyr   = cxr + 128;
    int* cxc   = cyr + 128;
    int* cyc   = cxc + 64;
    int* lut   = cyc + 64;

    const int tid = threadIdx.x;
    const int wid = tid >> 5;
    const int lane = tid & 31;
    const int gr = lane >> 2;
    const int q2 = (lane & 3) * 2;
    const int r0 = blockIdx.x * 128;
    const int h  = blockIdx.y;
    const int b  = blockIdx.z;
    const float alpha = alpha_p[0];

    const size_t kvbase = ((size_t)(b*HH + h))*NN*HD;

    // prologue: first K/V tile in flight
    attn_load_kv(sb + A2_KV, kvbase, 0, tid);
    CP_COMMIT();

    // bucket LUT
    for (int i = tid; i < 257; i += 256) {
        int rel = i - 128;
        int neg = -rel;
        int ret = (neg < 0) ? 16 : 0;
        int a = (neg < 0) ? -neg : neg;
        int bv;
        if (a < 8) bv = a;
        else {
            float t = logf((float)a * 0.125f) / 2.7725887222397811f * 8.0f;
            bv = 8 + (int)t;
            if (bv > 15) bv = 15;
        }
        lut[i] = ret + bv;
    }

    // load Q (hi/lo) into smem + row metadata
    const size_t qbase = (((size_t)(b*HH + h))*NN + r0)*HD;
#pragma unroll
    for (int it = 0; it < 4; it++) {
        int idx = it*256 + tid;
        int row = idx >> 3;
        int cg  = idx & 7;
        uint32_t off = (uint32_t)(row*128 + cg*16);
        uint32_t sw = off ^ ((off >> 3) & 0x70);
        *(uint4*)(sm + A2_QH + sw) = *(const uint4*)(g_qh + qbase + (size_t)row*HD + cg*8);
        *(uint4*)(sm + A2_QL + sw) = *(const uint4*)(g_ql + qbase + (size_t)row*HD + cg*8);
    }
    if (tid < 128) {
        int gidx = b*NN + r0 + tid;
        cxr[tid] = g_cx[gidx]; cyr[tid] = g_cy[gidx]; er[tid] = elev[gidx];
    }

    float m_i[2], l_i[2], oacc[8][4];
#pragma unroll
    for (int rr = 0; rr < 2; rr++) { m_i[rr] = -INFINITY; l_i[rr] = 0.0f; }
#pragma unroll
    for (int dt = 0; dt < 8; dt++)
#pragma unroll
        for (int r = 0; r < 4; r++) oacc[dt][r] = 0.0f;

    for (int t = 0; t < NN/64; t++) {
        const int c0 = t*64;
        __syncthreads();   // protects stage (t+1)&1 (computed at t-1) and meta
        if (t + 1 < NN/64) {
            attn_load_kv(sb + A2_KV + ((t+1)&1)*KV_STAGE, kvbase, c0 + 64, tid);
            CP_COMMIT();
        }
        if (tid < 64) {
            int gidx = b*NN + c0 + tid;
            cxc[tid] = g_cx[gidx]; cyc[tid] = g_cy[gidx]; ec[tid] = elev[gidx];
        }
        if (t + 1 < NN/64) CP_WAIT(1); else CP_WAIT(0);
        __syncthreads();

        const uint32_t kvb = sb + A2_KV + (t&1)*KV_STAGE;

        // ---- S = Q K^T ----
        float sacc[8][4];
#pragma unroll
        for (int nt = 0; nt < 8; nt++)
#pragma unroll
            for (int r = 0; r < 4; r++) sacc[nt][r] = 0.0f;

#pragma unroll
        for (int ks = 0; ks < 4; ks++) {
            int arow = wid*16 + (lane & 15);
            int acol = ks*32 + ((lane >> 4) << 4);
            uint32_t ah0, ah1, ah2, ah3, al0, al1, al2, al3;
            LDSM_X4(ah0, ah1, ah2, ah3, swz(sb + A2_QH, arow, acol));
            LDSM_X4(al0, al1, al2, al3, swz(sb + A2_QL, arow, acol));
#pragma unroll
            for (int g = 0; g < 4; g++) {
                int brow = g*16 + (lane & 15);
                int bcol = ks*32 + ((lane >> 4) << 4);
                uint32_t kh0, kh1, kh2, kh3, kl0, kl1, kl2, kl3;
                LDSM_X4(kh0, kh1, kh2, kh3, swz(kvb, brow, bcol));
                LDSM_X4(kl0, kl1, kl2, kl3, swz(kvb + 8192, brow, bcol));
                MMA16816(sacc[g*2+0], ah0, ah1, ah2, ah3, kh0, kh2);
                MMA16816(sacc[g*2+0], ah0, ah1, ah2, ah3, kl0, kl2);
                MMA16816(sacc[g*2+0], al0, al1, al2, al3, kh0, kh2);
                MMA16816(sacc[g*2+1], ah0, ah1, ah2, ah3, kh1, kh3);
                MMA16816(sacc[g*2+1], ah0, ah1, ah2, ah3, kl1, kl3);
                MMA16816(sacc[g*2+1], al0, al1, al2, al3, kh1, kh3);
            }
        }

        // ---- biases + online softmax ----
#pragma unroll
        for (int rr = 0; rr < 2; rr++) {
            int lrow = wid*16 + gr + rr*8;
            int cxi = cxr[lrow], cyi = cyr[lrow];
            float ei = er[lrow];
            float rm = -INFINITY;
#pragma unroll
            for (int nt = 0; nt < 8; nt++) {
#pragma unroll
                for (int e = 0; e < 2; e++) {
                    int lc = nt*8 + q2 + e;
                    int bx = lut[cxi - cxc[lc] + 128];
                    int by = lut[cyi - cyc[lc] + 128];
                    float rb = __ldg(btab + (bx*32 + by)*HH + h);
                    float diff = (ec[lc] - ei) * 0.001f;
                    float eb = fminf(fmaxf(-alpha * fmaxf(diff, 0.0f), -10.0f), 0.0f);
                    float s = sacc[nt][rr*2 + e] + rb + eb;
                    sacc[nt][rr*2 + e] = s;
                    rm = fmaxf(rm, s);
                }
            }
            rm = fmaxf(rm, __shfl_xor_sync(0xffffffffu, rm, 1));
            rm = fmaxf(rm, __shfl_xor_sync(0xffffffffu, rm, 2));
            float mn = fmaxf(m_i[rr], rm);
            float corr = __expf(m_i[rr] - mn);
            m_i[rr] = mn;
            float rs = 0.0f;
#pragma unroll
            for (int nt = 0; nt < 8; nt++) {
#pragma unroll
                for (int e = 0; e < 2; e++) {
                    float p = __expf(sacc[nt][rr*2 + e] - mn);
                    sacc[nt][rr*2 + e] = p;
                    rs += p;
                }
            }
            rs += __shfl_xor_sync(0xffffffffu, rs, 1);
            rs += __shfl_xor_sync(0xffffffffu, rs, 2);
            l_i[rr] = l_i[rr] * corr + rs;
#pragma unroll
            for (int dt = 0; dt < 8; dt++) {
                oacc[dt][rr*2 + 0] *= corr;
                oacc[dt][rr*2 + 1] *= corr;
            }
        }

        // ---- O += P V ----
#pragma unroll
        for (int kc = 0; kc < 4; kc++) {
            uint32_t pah0 = pack_hi(sacc[2*kc][0],   sacc[2*kc][1]);
            uint32_t pah1 = pack_hi(sacc[2*kc][2],   sacc[2*kc][3]);
            uint32_t pah2 = pack_hi(sacc[2*kc+1][0], sacc[2*kc+1][1]);
            uint32_t pah3 = pack_hi(sacc[2*kc+1][2], sacc[2*kc+1][3]);
            uint32_t pal0 = pack_lo(sacc[2*kc][0],   sacc[2*kc][1]);
            uint32_t pal1 = pack_lo(sacc[2*kc][2],   sacc[2*kc][3]);
            uint32_t pal2 = pack_lo(sacc[2*kc+1][0], sacc[2*kc+1][1]);
            uint32_t pal3 = pack_lo(sacc[2*kc+1][2], sacc[2*kc+1][3]);
#pragma unroll
            for (int dp = 0; dp < 4; dp++) {
                int vrow = kc*16 + (lane & 15);
                int vcol = dp*32 + ((lane >> 4) << 4);
                uint32_t vh0, vh1, vh2, vh3, vl0, vl1, vl2, vl3;
                LDSM_X4_T(vh0, vh1, vh2, vh3, swz(kvb + 16384, vrow, vcol));
                LDSM_X4_T(vl0, vl1, vl2, vl3, swz(kvb + 24576, vrow, vcol));
                MMA16816(oacc[dp*2+0], pah0, pah1, pah2, pah3, vh0, vh1);
                MMA16816(oacc[dp*2+0], pah0, pah1, pah2, pah3, vl0, vl1);
                MMA16816(oacc[dp*2+0], pal0, pal1, pal2, pal3, vh0, vh1);
                MMA16816(oacc[dp*2+1], pah0, pah1, pah2, pah3, vh2, vh3);
                MMA16816(oacc[dp*2+1], pah0, pah1, pah2, pah3, vl2, vl3);
                MMA16816(oacc[dp*2+1], pal0, pal1, pal2, pal3, vh2, vh3);
            }
        }
    }

    // ---- normalize + write bf16 hi/lo att ----
#pragma unroll
    for (int rr = 0; rr < 2; rr++) {
        float inv = 1.0f / l_i[rr];
        int row = r0 + wid*16 + gr + rr*8;
#pragma unroll
        for (int dt = 0; dt < 8; dt++) {
            float o0 = oacc[dt][rr*2+0] * inv;
            float o1 = oacc[dt][rr*2+1] * inv;
            size_t idx = ((size_t)b*NN + row)*DD + h*HD + dt*8 + q2;
            uint32_t hh = pack_hi(o0, o1);
            uint32_t ll = pack_lo(o0, o1);
            *(uint32_t*)(g_atth + idx) = hh;
            *(uint32_t*)(g_attl + idx) = ll;
        }
    }
}

// ---------------- launcher ----------------
extern "C" void kernel_launch(void* const* d_in, const int* in_sizes, int n_in,
                              void* d_out, int out_size) {
    const float* x       = (const float*)d_in[0];
    const float* coords  = (const float*)d_in[1];
    const float* elev    = (const float*)d_in[2];
    const float* qkv_w   = (const float*)d_in[3];
    const float* qkv_b   = (const float*)d_in[4];
    const float* proj_w  = (const float*)d_in[5];
    const float* proj_b  = (const float*)d_in[6];
    const float* btab    = (const float*)d_in[7];
    const float* alpha   = (const float*)d_in[8];
    float* out = (float*)d_out;

    prep_kernel<<<(BB*NN + 255)/256, 256>>>(coords);

    __nv_bfloat16 *xh, *xl, *wqh, *wql, *wph, *wpl;
    cudaGetSymbolAddress((void**)&xh,  g_xh);
    cudaGetSymbolAddress((void**)&xl,  g_xl);
    cudaGetSymbolAddress((void**)&wqh, g_wqh);
    cudaGetSymbolAddress((void**)&wql, g_wql);
    cudaGetSymbolAddress((void**)&wph, g_wph);
    cudaGetSymbolAddress((void**)&wpl, g_wpl);
    __nv_bfloat16 *ath, *atl;
    cudaGetSymbolAddress((void**)&ath, g_atth);
    cudaGetSymbolAddress((void**)&atl, g_attl);

    split_kernel<<<(MROWS*KDIM/4 + 255)/256, 256>>>(x, xh, xl, MROWS*KDIM);
    split_kernel<<<(3*DD*KDIM/4 + 255)/256, 256>>>(qkv_w, wqh, wql, 3*DD*KDIM);
    split_kernel<<<(DD*KDIM/4 + 255)/256, 256>>>(proj_w, wph, wpl, DD*KDIM);

    cudaFuncSetAttribute(mma_gemm<0>, cudaFuncAttributeMaxDynamicSharedMemorySize, GEMM_SMEM);
    cudaFuncSetAttribute(mma_gemm<1>, cudaFuncAttributeMaxDynamicSharedMemorySize, GEMM_SMEM);
    cudaFuncSetAttribute(attn_mma, cudaFuncAttributeMaxDynamicSharedMemorySize, ATTN2_SMEM);

    mma_gemm<0><<<dim3((3*DD)/128, MROWS/128), 256, GEMM_SMEM>>>(xh, xl, wqh, wql, qkv_b, nullptr);

    attn_mma<<<dim3(NN/128, HH, BB), 256, ATTN2_SMEM>>>(elev, btab, alpha);

    mma_gemm<1><<<dim3(DD/128, MROWS/128), 256, GEMM_SMEM>>>(ath, atl, wph, wpl, proj_b, out);
}